// round 9
// baseline (speedup 1.0000x reference)
#include <cuda_runtime.h>
#include <cuda_bf16.h>
#include <cstdint>

#define N_TOK 65536
#define D_IN  1024
#define E_DIM 256
#define K_CB  1024
#define EPS   1e-5f
#define SLABS 64

// smem tile geometry: rows of 32 bf16 (64B) padded to 80B
#define RB     80
#define ST_A   (128 * RB)                 // 10240
#define ST_B   (256 * RB)                 // 20480
#define STAGE  (2 * ST_A + 2 * ST_B)      // 61440: Ahi|Alo|Bhi|Blo
#define MM1_SMEM  (2 * STAGE + 2048)
#define DIST_SMEM (2 * STAGE + 4096)

// ================= scratch =================
__device__ float g_ps1[SLABS * D_IN];
__device__ float g_ps2[SLABS * D_IN];
__device__ float g_a[D_IN];
__device__ float g_bv[D_IN];
__device__ float g_b1p[E_DIM];
__device__ __nv_bfloat16 g_w1_hi[E_DIM * D_IN];
__device__ __nv_bfloat16 g_w1_lo[E_DIM * D_IN];
__device__ __nv_bfloat16 g_emb_hi[K_CB * E_DIM];
__device__ __nv_bfloat16 g_emb_lo[K_CB * E_DIM];
__device__ __nv_bfloat16 g_h_hi[(size_t)N_TOK * E_DIM];   // 32 MB
__device__ __nv_bfloat16 g_h_lo[(size_t)N_TOK * E_DIM];   // 32 MB
__device__ float g_hhp[N_TOK];
__device__ float g_ee[K_CB];
__device__ unsigned long long g_amin[N_TOK];
__device__ int   g_hist[K_CB];
__device__ float g_scale2[E_DIM];
__device__ float g_shift2[E_DIM];
__device__ float g_qn[K_CB * E_DIM];
__device__ float g_ocb[(size_t)K_CB * D_IN];
__device__ double g_loss;

// ================= helpers =================
__device__ __forceinline__ uint32_t smem_u32(const void* p) {
    uint32_t a;
    asm("{ .reg .u64 t; cvta.to.shared.u64 t, %1; cvt.u32.u64 %0, t; }" : "=r"(a) : "l"(p));
    return a;
}
__device__ __forceinline__ uint32_t pack2(__nv_bfloat16 a, __nv_bfloat16 b) {
    __nv_bfloat162 t(a, b); return *(uint32_t*)&t;
}
__device__ __forceinline__ void bf16split(float v, __nv_bfloat16& hi, __nv_bfloat16& lo) {
    hi = __float2bfloat16_rn(v);
    lo = __float2bfloat16_rn(v - __bfloat162float(hi));
}
__device__ __forceinline__ void mma_bf16(float c[4], const uint32_t a[4], const uint32_t b[2]) {
    asm volatile(
        "mma.sync.aligned.m16n8k16.row.col.f32.bf16.bf16.f32 "
        "{%0,%1,%2,%3}, {%4,%5,%6,%7}, {%8,%9}, {%0,%1,%2,%3};"
        : "+f"(c[0]), "+f"(c[1]), "+f"(c[2]), "+f"(c[3])
        : "r"(a[0]), "r"(a[1]), "r"(a[2]), "r"(a[3]), "r"(b[0]), "r"(b[1]));
}
__device__ __forceinline__ unsigned long long packdi(float d, unsigned col) {
    unsigned u = __float_as_uint(d);
    u = (u & 0x80000000u) ? ~u : (u | 0x80000000u);
    return ((unsigned long long)u << 32) | col;
}
__device__ __forceinline__ void cp16(uint32_t s, const void* g) {
    asm volatile("cp.async.cg.shared.global [%0], [%1], 16;" :: "r"(s), "l"(g));
}
#define CP_COMMIT() asm volatile("cp.async.commit_group;" ::: "memory")
#define CP_WAIT0()  asm volatile("cp.async.wait_group 0;" ::: "memory")
#define LDSM4(d, a) \
    asm volatile("ldmatrix.sync.aligned.m8n8.x4.shared.b16 {%0,%1,%2,%3}, [%4];" \
        : "=r"((d)[0]), "=r"((d)[1]), "=r"((d)[2]), "=r"((d)[3]) : "r"(a))

// shared MMA block: warp tile 64(m) x 64(n), K=32 chunk, bf16x3
__device__ __forceinline__ void mma_block(uint32_t cb, uint32_t aOff, uint32_t bOff,
                                          float acc[4][8][4]) {
#pragma unroll
    for (int s = 0; s < 2; s++) {
        uint32_t sB = s * 32;
        uint32_t ah[4][4], al[4][4];
#pragma unroll
        for (int mi = 0; mi < 4; mi++) {
            uint32_t ad = cb + aOff + mi * (16 * RB) + sB;
            LDSM4(ah[mi], ad);
            LDSM4(al[mi], ad + ST_A);
        }
#pragma unroll
        for (int p = 0; p < 4; p++) {
            uint32_t bd = cb + 2 * ST_A + bOff + p * (16 * RB) + sB;
            uint32_t bh[4], bl[4];
            LDSM4(bh, bd);
            LDSM4(bl, bd + ST_B);
#pragma unroll
            for (int mi = 0; mi < 4; mi++)
#pragma unroll
                for (int q = 0; q < 2; q++) {
                    mma_bf16(acc[mi][2 * p + q], ah[mi], &bh[q * 2]);
                    mma_bf16(acc[mi][2 * p + q], ah[mi], &bl[q * 2]);
                    mma_bf16(acc[mi][2 * p + q], al[mi], &bh[q * 2]);
                }
        }
    }
}

// ================= producers =================
__global__ void k_colstats(const float* __restrict__ x) {
    int col  = blockIdx.x * 256 + threadIdx.x;
    int slab = blockIdx.y;
    const float* p = x + (size_t)slab * 1024 * D_IN + col;
    float s = 0.f, s2 = 0.f;
#pragma unroll 8
    for (int r = 0; r < 1024; r++) { float v = p[(size_t)r * D_IN]; s += v; s2 += v * v; }
    g_ps1[slab * D_IN + col] = s;
    g_ps2[slab * D_IN + col] = s2;
}

__global__ void k_bn1fin(const float* __restrict__ gamma1, const float* __restrict__ beta1) {
    int col = blockIdx.x * 256 + threadIdx.x;
    float s = 0.f, s2 = 0.f;
    for (int i = 0; i < SLABS; i++) { s += g_ps1[i * D_IN + col]; s2 += g_ps2[i * D_IN + col]; }
    float mu  = s / (float)N_TOK;
    float var = s2 / (float)N_TOK - mu * mu;
    float a = gamma1[col] * rsqrtf(var + EPS);
    g_a[col]  = a;
    g_bv[col] = beta1[col] - mu * a;
}

__global__ void k_fold(const float* __restrict__ w1, const float* __restrict__ b1) {
    int e = blockIdx.x, t = threadIdx.x;
    float acc = 0.f;
#pragma unroll
    for (int j = 0; j < D_IN / 256; j++) {
        int d = j * 256 + t;
        float w = w1[(size_t)e * D_IN + d];
        float ws = w * g_a[d];
        __nv_bfloat16 hi, lo; bf16split(ws, hi, lo);
        g_w1_hi[(size_t)e * D_IN + d] = hi;
        g_w1_lo[(size_t)e * D_IN + d] = lo;
        acc += g_bv[d] * w;
    }
    __shared__ float sm[256];
    sm[t] = acc; __syncthreads();
    for (int s = 128; s > 0; s >>= 1) { if (t < s) sm[t] += sm[t + s]; __syncthreads(); }
    if (t == 0) g_b1p[e] = b1[e] + sm[0];
}

__global__ void k_ee(const float* __restrict__ emb) {
    int warp = threadIdx.x >> 5, lane = threadIdx.x & 31;
    int row = blockIdx.x * 8 + warp;
    const float* p = emb + (size_t)row * E_DIM;
    float s = 0.f;
#pragma unroll
    for (int c = lane; c < E_DIM; c += 32) {
        float v = p[c]; s += v * v;
        __nv_bfloat16 hi, lo; bf16split(v, hi, lo);
        g_emb_hi[(size_t)row * E_DIM + c] = hi;
        g_emb_lo[(size_t)row * E_DIM + c] = lo;
    }
#pragma unroll
    for (int o = 16; o > 0; o >>= 1) s += __shfl_down_sync(0xffffffffu, s, o);
    if (lane == 0) g_ee[row] = s;
}

__global__ void k_init() {
    int i = blockIdx.x * 256 + threadIdx.x;   // 1024 threads
    g_hist[i] = 0;
    if (i == 0) g_loss = 0.0;
}

// ================= GEMM1: 128x256 CTA, x fp32 inline-split =================
__device__ __forceinline__ void mm1_fillB(uint32_t sbuf, int kOff) {
    int tid = threadIdx.x;
#pragma unroll
    for (int j = 0; j < 4; j++) {
        int idx = tid * 4 + j;           // 1024 tasks: 256 rows x 4 segs
        int row = idx >> 2, seg = idx & 3;
        uint32_t so = 2 * ST_A + (uint32_t)(row * RB + seg * 16);
        const char* ph = (const char*)(g_w1_hi + (size_t)row * D_IN + kOff) + seg * 16;
        const char* pl = (const char*)(g_w1_lo + (size_t)row * D_IN + kOff) + seg * 16;
        cp16(sbuf + so, ph);
        cp16(sbuf + so + ST_B, pl);
    }
}
__device__ __forceinline__ void mm1_loadA(float4 ar[4], const float* Asrc, int kOff) {
    int row = threadIdx.x >> 1, cb = (threadIdx.x & 1) * 16;
    const float4* p = (const float4*)(Asrc + (size_t)row * D_IN + kOff + cb);
#pragma unroll
    for (int i = 0; i < 4; i++) ar[i] = p[i];
}
__device__ __forceinline__ void mm1_cvtA(char* stage, const float4 ar[4]) {
    int row = threadIdx.x >> 1, cb = (threadIdx.x & 1) * 16;
#pragma unroll
    for (int i = 0; i < 4; i++) {
        __nv_bfloat16 h0, h1, h2, h3, l0, l1, l2, l3;
        bf16split(ar[i].x, h0, l0); bf16split(ar[i].y, h1, l1);
        bf16split(ar[i].z, h2, l2); bf16split(ar[i].w, h3, l3);
        uint2 uh; uh.x = pack2(h0, h1); uh.y = pack2(h2, h3);
        uint2 ul; ul.x = pack2(l0, l1); ul.y = pack2(l2, l3);
        uint32_t off = (uint32_t)(row * RB + (cb + i * 4) * 2);
        *(uint2*)(stage + off) = uh;
        *(uint2*)(stage + ST_A + off) = ul;
    }
}

__global__ __launch_bounds__(256, 1) void k_mm1(const float* __restrict__ x) {
    extern __shared__ char smc[];
    uint32_t sb = smem_u32(smc);
    float* hh_sm = (float*)(smc + 2 * STAGE);
    int tid = threadIdx.x, lane = tid & 31, warp = tid >> 5;
    int wm = warp & 1, wn = warp >> 1, g = lane >> 2, tig = lane & 3;
    uint32_t aOff = (uint32_t)((wm * 64 + ((lane >> 3) & 1) * 8 + (lane & 7)) * RB + (lane >> 4) * 16);
    uint32_t bOff = (uint32_t)((wn * 64 + ((lane >> 4) & 1) * 8 + (lane & 7)) * RB + ((lane >> 3) & 1) * 16);
    const float* Asrc = x + (size_t)blockIdx.x * 128 * D_IN;

    float acc[4][8][4] = {};
    float4 ar[4];

    mm1_fillB(sb, 0);
    mm1_loadA(ar, Asrc, 0);
    mm1_cvtA(smc, ar);
    CP_COMMIT();

    for (int c = 0; c < 32; c++) {
        uint32_t cb = sb + (uint32_t)(c & 1) * STAGE;
        char* nxt = smc + (size_t)((c + 1) & 1) * STAGE;
        CP_WAIT0();
        __syncthreads();
        if (c < 31) {
            mm1_fillB(sb + (uint32_t)((c + 1) & 1) * STAGE, (c + 1) * 32);
            CP_COMMIT();
            mm1_loadA(ar, Asrc, (c + 1) * 32);
        }
        mma_block(cb, aOff, bOff, acc);
        if (c < 31) mm1_cvtA(nxt, ar);
    }

    // epilogue: bias + full hh + bf16 split of h
    float bv0[8], bv1[8];
#pragma unroll
    for (int ni = 0; ni < 8; ni++) {
        int colg = wn * 64 + ni * 8 + tig * 2;
        bv0[ni] = g_b1p[colg]; bv1[ni] = g_b1p[colg + 1];
    }
#pragma unroll
    for (int mi = 0; mi < 4; mi++) {
        int rloc = wm * 64 + mi * 16 + g;
        int rowg = blockIdx.x * 128 + rloc;
        float s0 = 0.f, s1 = 0.f;
#pragma unroll
        for (int ni = 0; ni < 8; ni++) {
            int colg = wn * 64 + ni * 8 + tig * 2;
            float v0 = acc[mi][ni][0] + bv0[ni];
            float v1 = acc[mi][ni][1] + bv1[ni];
            float v2 = acc[mi][ni][2] + bv0[ni];
            float v3 = acc[mi][ni][3] + bv1[ni];
            s0 += v0 * v0 + v1 * v1;
            s1 += v2 * v2 + v3 * v3;
            __nv_bfloat16 h0, h1, l0, l1;
            bf16split(v0, h0, l0); bf16split(v1, h1, l1);
            *(uint32_t*)(g_h_hi + (size_t)rowg * 256 + colg) = pack2(h0, h1);
            *(uint32_t*)(g_h_lo + (size_t)rowg * 256 + colg) = pack2(l0, l1);
            bf16split(v2, h0, l0); bf16split(v3, h1, l1);
            *(uint32_t*)(g_h_hi + (size_t)(rowg + 8) * 256 + colg) = pack2(h0, h1);
            *(uint32_t*)(g_h_lo + (size_t)(rowg + 8) * 256 + colg) = pack2(l0, l1);
        }
        s0 += __shfl_xor_sync(0xffffffffu, s0, 1);
        s0 += __shfl_xor_sync(0xffffffffu, s0, 2);
        s1 += __shfl_xor_sync(0xffffffffu, s1, 1);
        s1 += __shfl_xor_sync(0xffffffffu, s1, 2);
        if (tig == 0) { hh_sm[wn * 128 + rloc] = s0; hh_sm[wn * 128 + rloc + 8] = s1; }
    }
    __syncthreads();
    if (tid < 128) {
        g_hhp[blockIdx.x * 128 + tid] =
            hh_sm[tid] + hh_sm[128 + tid] + hh_sm[256 + tid] + hh_sm[384 + tid];
    }
}

// ================= dist: per-CTA full K_CB, no atomics =================
__device__ __forceinline__ void dist_fill(uint32_t sbuf,
    const __nv_bfloat16* Ah, const __nv_bfloat16* Al, int kOff,
    const __nv_bfloat16* Bh, const __nv_bfloat16* Bl) {
    int tid = threadIdx.x;
#pragma unroll
    for (int j = 0; j < 2; j++) {
        int idx = tid * 2 + j;           // 512 tasks: 128 rows x 4 segs
        int row = idx >> 2, seg = idx & 3;
        uint32_t so = (uint32_t)(row * RB + seg * 16);
        cp16(sbuf + so,        (const char*)(Ah + (size_t)row * E_DIM + kOff) + seg * 16);
        cp16(sbuf + so + ST_A, (const char*)(Al + (size_t)row * E_DIM + kOff) + seg * 16);
    }
#pragma unroll
    for (int j = 0; j < 4; j++) {
        int idx = tid * 4 + j;           // 1024 tasks: 256 rows x 4 segs
        int row = idx >> 2, seg = idx & 3;
        uint32_t so = 2 * ST_A + (uint32_t)(row * RB + seg * 16);
        cp16(sbuf + so,        (const char*)(Bh + (size_t)row * E_DIM + kOff) + seg * 16);
        cp16(sbuf + so + ST_B, (const char*)(Bl + (size_t)row * E_DIM + kOff) + seg * 16);
    }
}

__global__ __launch_bounds__(256, 1) void k_dist() {
    extern __shared__ char smc[];
    uint32_t sb = smem_u32(smc);
    unsigned long long* red = (unsigned long long*)(smc + 2 * STAGE);
    int tid = threadIdx.x, lane = tid & 31, warp = tid >> 5;
    int wm = warp & 1, wn = warp >> 1, g = lane >> 2, tig = lane & 3;
    uint32_t aOff = (uint32_t)((wm * 64 + ((lane >> 3) & 1) * 8 + (lane & 7)) * RB + (lane >> 4) * 16);
    uint32_t bOff = (uint32_t)((wn * 64 + ((lane >> 4) & 1) * 8 + (lane & 7)) * RB + ((lane >> 3) & 1) * 16);
    const __nv_bfloat16* Ah = g_h_hi + (size_t)blockIdx.x * 128 * E_DIM;
    const __nv_bfloat16* Al = g_h_lo + (size_t)blockIdx.x * 128 * E_DIM;

    red[tid] = ~0ull; red[tid + 256] = ~0ull;
    __syncthreads();

    for (int nb = 0; nb < 4; nb++) {
        const __nv_bfloat16* Bh = g_emb_hi + (size_t)nb * 256 * E_DIM;
        const __nv_bfloat16* Bl = g_emb_lo + (size_t)nb * 256 * E_DIM;
        float acc[4][8][4] = {};

        dist_fill(sb, Ah, Al, 0, Bh, Bl);
        CP_COMMIT();
        for (int c = 0; c < 8; c++) {
            uint32_t cb = sb + (uint32_t)(c & 1) * STAGE;
            CP_WAIT0();
            __syncthreads();
            if (c < 7) {
                dist_fill(sb + (uint32_t)((c + 1) & 1) * STAGE, Ah, Al, (c + 1) * 32, Bh, Bl);
                CP_COMMIT();
            }
            mma_block(cb, aOff, bOff, acc);
        }

        // epilogue for this 256-code block
#pragma unroll
        for (int mi = 0; mi < 4; mi++) {
            int rloc = wm * 64 + mi * 16 + g;
            int rowg = blockIdx.x * 128 + rloc;
            float hh0 = g_hhp[rowg];
            float hh1 = g_hhp[rowg + 8];
            unsigned long long b0 = ~0ull, b1 = ~0ull;
#pragma unroll
            for (int ni = 0; ni < 8; ni++) {
                int colg = nb * 256 + wn * 64 + ni * 8 + tig * 2;
                float e0 = g_ee[colg], e1 = g_ee[colg + 1];
                float d0 = __fsub_rn(__fadd_rn(hh0, e0), __fmul_rn(2.0f, acc[mi][ni][0]));
                float d1 = __fsub_rn(__fadd_rn(hh0, e1), __fmul_rn(2.0f, acc[mi][ni][1]));
                float d2 = __fsub_rn(__fadd_rn(hh1, e0), __fmul_rn(2.0f, acc[mi][ni][2]));
                float d3 = __fsub_rn(__fadd_rn(hh1, e1), __fmul_rn(2.0f, acc[mi][ni][3]));
                unsigned long long p;
                p = packdi(d0, colg);     if (p < b0) b0 = p;
                p = packdi(d1, colg + 1); if (p < b0) b0 = p;
                p = packdi(d2, colg);     if (p < b1) b1 = p;
                p = packdi(d3, colg + 1); if (p < b1) b1 = p;
            }
            unsigned long long t;
            t = __shfl_xor_sync(0xffffffffu, b0, 1); if (t < b0) b0 = t;
            t = __shfl_xor_sync(0xffffffffu, b0, 2); if (t < b0) b0 = t;
            t = __shfl_xor_sync(0xffffffffu, b1, 1); if (t < b1) b1 = t;
            t = __shfl_xor_sync(0xffffffffu, b1, 2); if (t < b1) b1 = t;
            if (tig == 0) {
                unsigned long long* r0 = &red[wn * 128 + rloc];
                unsigned long long* r1 = &red[wn * 128 + rloc + 8];
                if (b0 < *r0) *r0 = b0;
                if (b1 < *r1) *r1 = b1;
            }
        }
        __syncthreads();
    }

    if (tid < 128) {
        unsigned long long m = red[tid];
        unsigned long long v;
        v = red[128 + tid]; if (v < m) m = v;
        v = red[256 + tid]; if (v < m) m = v;
        v = red[384 + tid]; if (v < m) m = v;
        g_amin[blockIdx.x * 128 + tid] = m;
    }
}

// ================= rest of pipeline (validated) =================
__global__ void k_histo() {
    __shared__ int sh[K_CB];
    int t = threadIdx.x;
    for (int i = t; i < K_CB; i += 256) sh[i] = 0;
    __syncthreads();
    int n = blockIdx.x * 256 + t;
    int idx = (int)(g_amin[n] & 0xFFFFFFFFull);
    atomicAdd(&sh[idx], 1);
    __syncthreads();
    for (int i = t; i < K_CB; i += 256) if (sh[i]) atomicAdd(&g_hist[i], sh[i]);
}

__global__ void k_bn2(const float* __restrict__ emb,
                      const float* __restrict__ gamma2, const float* __restrict__ beta2) {
    int e = blockIdx.x, t = threadIdx.x;
    float s1 = 0.f, s2 = 0.f;
#pragma unroll
    for (int j = 0; j < 4; j++) {
        int k = j * 256 + t;
        float c = (float)g_hist[k];
        float v = emb[(size_t)k * E_DIM + e];
        s1 += c * v; s2 += c * v * v;
    }
    __shared__ float a1[256], a2[256];
    a1[t] = s1; a2[t] = s2; __syncthreads();
    for (int s = 128; s > 0; s >>= 1) {
        if (t < s) { a1[t] += a1[t + s]; a2[t] += a2[t + s]; }
        __syncthreads();
    }
    if (t == 0) {
        float mu  = a1[0] / (float)N_TOK;
        float var = a2[0] / (float)N_TOK - mu * mu;
        float sc = gamma2[e] * rsqrtf(var + EPS);
        g_scale2[e] = sc;
        g_shift2[e] = beta2[e] - mu * sc;
    }
}

__global__ void k_qn(const float* __restrict__ emb) {
    int i = blockIdx.x * 256 + threadIdx.x;
    int e = i & (E_DIM - 1);
    g_qn[i] = emb[i] * g_scale2[e] + g_shift2[e];
}

__global__ void k_gemm2(const float* __restrict__ w2, const float* __restrict__ b2) {
    __shared__ float As[16][128];
    __shared__ float Bs[16][128];
    float acc[8][8] = {};
    int tid = threadIdx.x;
    int tx = tid & 15, ty = tid >> 4;
    const float* Ab = g_qn + (size_t)(blockIdx.x * 128) * E_DIM;
    const float* Bb = w2 + (size_t)(blockIdx.y * 128) * E_DIM;
    for (int k0 = 0; k0 < E_DIM; k0 += 16) {
#pragma unroll
        for (int i = 0; i < 2; i++) {
            int id  = tid + i * 256;
            int row = id >> 2;
            int kq  = (id & 3) << 2;
            float4 va = *(const float4*)(Ab + (size_t)row * E_DIM + k0 + kq);
            As[kq + 0][row] = va.x; As[kq + 1][row] = va.y;
            As[kq + 2][row] = va.z; As[kq + 3][row] = va.w;
            float4 vb = *(const float4*)(Bb + (size_t)row * E_DIM + k0 + kq);
            Bs[kq + 0][row] = vb.x; Bs[kq + 1][row] = vb.y;
            Bs[kq + 2][row] = vb.z; Bs[kq + 3][row] = vb.w;
        }
        __syncthreads();
#pragma unroll
        for (int kk = 0; kk < 16; kk++) {
            float ra[8], rb[8];
            *(float4*)&ra[0] = *(const float4*)&As[kk][ty * 8];
            *(float4*)&ra[4] = *(const float4*)&As[kk][ty * 8 + 4];
            *(float4*)&rb[0] = *(const float4*)&Bs[kk][tx * 8];
            *(float4*)&rb[4] = *(const float4*)&Bs[kk][tx * 8 + 4];
#pragma unroll
            for (int i = 0; i < 8; i++)
#pragma unroll
                for (int j = 0; j < 8; j++)
                    acc[i][j] += ra[i] * rb[j];
        }
        __syncthreads();
    }
    int colBase = blockIdx.y * 128 + tx * 8;
#pragma unroll
    for (int i = 0; i < 8; i++) {
        size_t row = (size_t)blockIdx.x * 128 + ty * 8 + i;
        float4 v0, v1;
        v0.x = acc[i][0] + b2[colBase + 0]; v0.y = acc[i][1] + b2[colBase + 1];
        v0.z = acc[i][2] + b2[colBase + 2]; v0.w = acc[i][3] + b2[colBase + 3];
        v1.x = acc[i][4] + b2[colBase + 4]; v1.y = acc[i][5] + b2[colBase + 5];
        v1.z = acc[i][6] + b2[colBase + 6]; v1.w = acc[i][7] + b2[colBase + 7];
        *(float4*)(g_ocb + row * D_IN + colBase)     = v0;
        *(float4*)(g_ocb + row * D_IN + colBase + 4) = v1;
    }
}

__global__ void k_final(const float* __restrict__ x, float* __restrict__ out) {
    int t = threadIdx.x;
    float* outq = out + 1;
    double accd = 0.0;
#pragma unroll
    for (int r = 0; r < 8; r++) {
        int n = blockIdx.x * 8 + r;
        int idx = (int)(g_amin[n] & 0xFFFFFFFFull);
        float4 q  = ((const float4*)(g_ocb + (size_t)idx * D_IN))[t];
        float4 xv = ((const float4*)(x + (size_t)n * D_IN))[t];
        float dx = __fsub_rn(q.x, xv.x);
        float dy = __fsub_rn(q.y, xv.y);
        float dz = __fsub_rn(q.z, xv.z);
        float dw = __fsub_rn(q.w, xv.w);
        float* o = outq + (size_t)n * D_IN + t * 4;
        o[0] = __fadd_rn(xv.x, dx);
        o[1] = __fadd_rn(xv.y, dy);
        o[2] = __fadd_rn(xv.z, dz);
        o[3] = __fadd_rn(xv.w, dw);
        accd += (double)dx * dx + (double)dy * dy + (double)dz * dz + (double)dw * dw;
    }
    __shared__ double sd[256];
    sd[t] = accd; __syncthreads();
    for (int s = 128; s > 0; s >>= 1) { if (t < s) sd[t] += sd[t + s]; __syncthreads(); }
    if (t == 0) atomicAdd(&g_loss, sd[0]);
}

__global__ void k_small(float* __restrict__ out) {
    int i = blockIdx.x * 256 + threadIdx.x;
    size_t OFF_U = 1 + (size_t)N_TOK * D_IN;
    if (i == 0) out[0] = (float)(1.25 * g_loss / ((double)N_TOK * (double)D_IN));
    if (i < K_CB) out[OFF_U + i] = (float)g_hist[i] / (float)N_TOK;
}

__global__ void k_embcopy(const float* __restrict__ emb, float* __restrict__ out) {
    size_t OFF_E = 1 + (size_t)N_TOK * D_IN + K_CB;
    int i = blockIdx.x * 256 + threadIdx.x;
    out[OFF_E + i] = emb[i];
}

// ================= launch (k_mm1 moved to slot 3 for ncu) =================
extern "C" void kernel_launch(void* const* d_in, const int* in_sizes, int n_in,
                              void* d_out, int out_size) {
    (void)in_sizes; (void)n_in; (void)out_size;
    const float* x      = (const float*)d_in[0];
    const float* emb    = (const float*)d_in[1];
    const float* w1     = (const float*)d_in[2];
    const float* b1     = (const float*)d_in[3];
    const float* w2     = (const float*)d_in[4];
    const float* b2     = (const float*)d_in[5];
    const float* gamma1 = (const float*)d_in[6];
    const float* beta1  = (const float*)d_in[7];
    const float* gamma2 = (const float*)d_in[8];
    const float* beta2  = (const float*)d_in[9];
    float* out = (float*)d_out;

    cudaFuncSetAttribute(k_mm1,  cudaFuncAttributeMaxDynamicSharedMemorySize, MM1_SMEM);
    cudaFuncSetAttribute(k_dist, cudaFuncAttributeMaxDynamicSharedMemorySize, DIST_SMEM);

    k_colstats<<<dim3(D_IN / 256, SLABS), 256>>>(x);        // 0
    k_bn1fin<<<D_IN / 256, 256>>>(gamma1, beta1);           // 1
    k_fold<<<E_DIM, 256>>>(w1, b1);                         // 2
    k_mm1<<<N_TOK / 128, 256, MM1_SMEM>>>(x);               // 3  <- ncu slot
    k_ee<<<K_CB / 8, 256>>>(emb);                           // 4
    k_dist<<<N_TOK / 128, 256, DIST_SMEM>>>();              // 5
    k_init<<<4, 256>>>();                                   // 6
    k_histo<<<N_TOK / 256, 256>>>();                        // 7
    k_bn2<<<E_DIM, 256>>>(emb, gamma2, beta2);              // 8
    k_qn<<<(K_CB * E_DIM) / 256, 256>>>(emb);               // 9
    k_gemm2<<<dim3(K_CB / 128, D_IN / 128), 256>>>(w2, b2); // 10
    k_final<<<N_TOK / 8, 256>>>(x, out);                    // 11
    k_small<<<4, 256>>>(out);                               // 12
    k_embcopy<<<(K_CB * E_DIM) / 256, 256>>>(emb, out);     // 13
}

// round 10
// speedup vs baseline: 1.1177x; 1.1177x over previous
#include <cuda_runtime.h>
#include <cuda_bf16.h>
#include <cstdint>

#define N_TOK 65536
#define D_IN  1024
#define E_DIM 256
#define K_CB  1024
#define EPS   1e-5f
#define SLABS 64

// smem tile geometry: rows of 32 bf16 (64B) padded to 80B
#define RB     80
#define ST_A   (128 * RB)                 // 10240
#define ST_B   (256 * RB)                 // 20480
#define STAGE  (2 * ST_A + 2 * ST_B)      // 61440: Ahi|Alo|Bhi|Blo
#define MM1_SMEM  (2 * STAGE + 2048)
#define DIST_SMEM (2 * STAGE + 4096)

// ================= scratch =================
__device__ float g_ps1[SLABS * D_IN];
__device__ float g_ps2[SLABS * D_IN];
__device__ float g_a[D_IN];
__device__ float g_bv[D_IN];
__device__ float g_b1p[E_DIM];
__device__ __nv_bfloat16 g_w1_hi[E_DIM * D_IN];
__device__ __nv_bfloat16 g_w1_lo[E_DIM * D_IN];
__device__ __nv_bfloat16 g_emb_hi[K_CB * E_DIM];
__device__ __nv_bfloat16 g_emb_lo[K_CB * E_DIM];
__device__ __nv_bfloat16 g_h_hi[(size_t)N_TOK * E_DIM];   // 32 MB
__device__ __nv_bfloat16 g_h_lo[(size_t)N_TOK * E_DIM];   // 32 MB
__device__ float g_hhp[N_TOK];
__device__ float g_ee[K_CB];
__device__ unsigned long long g_amin[N_TOK];
__device__ int   g_hist[K_CB];
__device__ float g_scale2[E_DIM];
__device__ float g_shift2[E_DIM];
__device__ float g_qn[K_CB * E_DIM];
__device__ float g_ocb[(size_t)K_CB * D_IN];
__device__ double g_loss;

// ================= helpers =================
__device__ __forceinline__ uint32_t smem_u32(const void* p) {
    uint32_t a;
    asm("{ .reg .u64 t; cvta.to.shared.u64 t, %1; cvt.u32.u64 %0, t; }" : "=r"(a) : "l"(p));
    return a;
}
__device__ __forceinline__ uint32_t pack2(__nv_bfloat16 a, __nv_bfloat16 b) {
    __nv_bfloat162 t(a, b); return *(uint32_t*)&t;
}
__device__ __forceinline__ void bf16split(float v, __nv_bfloat16& hi, __nv_bfloat16& lo) {
    hi = __float2bfloat16_rn(v);
    lo = __float2bfloat16_rn(v - __bfloat162float(hi));
}
__device__ __forceinline__ void mma_bf16(float c[4], const uint32_t a[4], const uint32_t b[2]) {
    asm volatile(
        "mma.sync.aligned.m16n8k16.row.col.f32.bf16.bf16.f32 "
        "{%0,%1,%2,%3}, {%4,%5,%6,%7}, {%8,%9}, {%0,%1,%2,%3};"
        : "+f"(c[0]), "+f"(c[1]), "+f"(c[2]), "+f"(c[3])
        : "r"(a[0]), "r"(a[1]), "r"(a[2]), "r"(a[3]), "r"(b[0]), "r"(b[1]));
}
__device__ __forceinline__ unsigned long long packdi(float d, unsigned col) {
    unsigned u = __float_as_uint(d);
    u = (u & 0x80000000u) ? ~u : (u | 0x80000000u);
    return ((unsigned long long)u << 32) | col;
}
__device__ __forceinline__ void cp16(uint32_t s, const void* g) {
    asm volatile("cp.async.cg.shared.global [%0], [%1], 16;" :: "r"(s), "l"(g));
}
#define CP_COMMIT() asm volatile("cp.async.commit_group;" ::: "memory")
#define CP_WAIT0()  asm volatile("cp.async.wait_group 0;" ::: "memory")
#define LDSM4(d, a) \
    asm volatile("ldmatrix.sync.aligned.m8n8.x4.shared.b16 {%0,%1,%2,%3}, [%4];" \
        : "=r"((d)[0]), "=r"((d)[1]), "=r"((d)[2]), "=r"((d)[3]) : "r"(a))

// MMA block: warp tile 32(m) x 64(n), K=32 chunk, bf16x3
__device__ __forceinline__ void mma_block(uint32_t cb, uint32_t aOff, uint32_t bOff,
                                          float acc[2][8][4]) {
#pragma unroll
    for (int s = 0; s < 2; s++) {
        uint32_t sB = s * 32;
        uint32_t ah[2][4], al[2][4];
#pragma unroll
        for (int mi = 0; mi < 2; mi++) {
            uint32_t ad = cb + aOff + mi * (16 * RB) + sB;
            LDSM4(ah[mi], ad);
            LDSM4(al[mi], ad + ST_A);
        }
#pragma unroll
        for (int p = 0; p < 4; p++) {
            uint32_t bd = cb + 2 * ST_A + bOff + p * (16 * RB) + sB;
            uint32_t bh[4], bl[4];
            LDSM4(bh, bd);
            LDSM4(bl, bd + ST_B);
#pragma unroll
            for (int mi = 0; mi < 2; mi++)
#pragma unroll
                for (int q = 0; q < 2; q++) {
                    mma_bf16(acc[mi][2 * p + q], ah[mi], &bh[q * 2]);
                    mma_bf16(acc[mi][2 * p + q], ah[mi], &bl[q * 2]);
                    mma_bf16(acc[mi][2 * p + q], al[mi], &bh[q * 2]);
                }
        }
    }
}

// ================= producers =================
__global__ void k_colstats(const float* __restrict__ x) {
    int col  = blockIdx.x * 256 + threadIdx.x;
    int slab = blockIdx.y;
    const float* p = x + (size_t)slab * 1024 * D_IN + col;
    float s = 0.f, s2 = 0.f;
#pragma unroll 8
    for (int r = 0; r < 1024; r++) { float v = p[(size_t)r * D_IN]; s += v; s2 += v * v; }
    g_ps1[slab * D_IN + col] = s;
    g_ps2[slab * D_IN + col] = s2;
}

__global__ void k_bn1fin(const float* __restrict__ gamma1, const float* __restrict__ beta1) {
    int col = blockIdx.x * 256 + threadIdx.x;
    float s = 0.f, s2 = 0.f;
    for (int i = 0; i < SLABS; i++) { s += g_ps1[i * D_IN + col]; s2 += g_ps2[i * D_IN + col]; }
    float mu  = s / (float)N_TOK;
    float var = s2 / (float)N_TOK - mu * mu;
    float a = gamma1[col] * rsqrtf(var + EPS);
    g_a[col]  = a;
    g_bv[col] = beta1[col] - mu * a;
}

__global__ void k_fold(const float* __restrict__ w1, const float* __restrict__ b1) {
    int e = blockIdx.x, t = threadIdx.x;
    float acc = 0.f;
#pragma unroll
    for (int j = 0; j < D_IN / 256; j++) {
        int d = j * 256 + t;
        float w = w1[(size_t)e * D_IN + d];
        float ws = w * g_a[d];
        __nv_bfloat16 hi, lo; bf16split(ws, hi, lo);
        g_w1_hi[(size_t)e * D_IN + d] = hi;
        g_w1_lo[(size_t)e * D_IN + d] = lo;
        acc += g_bv[d] * w;
    }
    __shared__ float sm[256];
    sm[t] = acc; __syncthreads();
    for (int s = 128; s > 0; s >>= 1) { if (t < s) sm[t] += sm[t + s]; __syncthreads(); }
    if (t == 0) g_b1p[e] = b1[e] + sm[0];
}

__global__ void k_ee(const float* __restrict__ emb) {
    int warp = threadIdx.x >> 5, lane = threadIdx.x & 31;
    int row = blockIdx.x * 8 + warp;
    const float* p = emb + (size_t)row * E_DIM;
    float s = 0.f;
#pragma unroll
    for (int c = lane; c < E_DIM; c += 32) {
        float v = p[c]; s += v * v;
        __nv_bfloat16 hi, lo; bf16split(v, hi, lo);
        g_emb_hi[(size_t)row * E_DIM + c] = hi;
        g_emb_lo[(size_t)row * E_DIM + c] = lo;
    }
#pragma unroll
    for (int o = 16; o > 0; o >>= 1) s += __shfl_down_sync(0xffffffffu, s, o);
    if (lane == 0) g_ee[row] = s;
}

__global__ void k_init() {
    int i = blockIdx.x * 256 + threadIdx.x;
    g_hist[i] = 0;
    if (i == 0) g_loss = 0.0;
}

// ================= GEMM1: 128x256 CTA, 512 thr, warp 32x64 =================
__device__ __forceinline__ void mm1_fillB(uint32_t sbuf, int kOff) {
    int tid = threadIdx.x;
#pragma unroll
    for (int j = 0; j < 2; j++) {
        int idx = tid * 2 + j;           // 1024 tasks: 256 rows x 4 segs
        int row = idx >> 2, seg = idx & 3;
        uint32_t so = 2 * ST_A + (uint32_t)(row * RB + seg * 16);
        cp16(sbuf + so,        (const char*)(g_w1_hi + (size_t)row * D_IN + kOff) + seg * 16);
        cp16(sbuf + so + ST_B, (const char*)(g_w1_lo + (size_t)row * D_IN + kOff) + seg * 16);
    }
}
__device__ __forceinline__ void mm1_loadA(float4 ar[2], const float* Asrc, int kOff) {
    int row = threadIdx.x >> 2, cb = (threadIdx.x & 3) * 8;
    const float4* p = (const float4*)(Asrc + (size_t)row * D_IN + kOff + cb);
    ar[0] = p[0]; ar[1] = p[1];
}
__device__ __forceinline__ void mm1_cvtA(char* stage, const float4 ar[2]) {
    int row = threadIdx.x >> 2, cb = (threadIdx.x & 3) * 8;
#pragma unroll
    for (int i = 0; i < 2; i++) {
        __nv_bfloat16 h0, h1, h2, h3, l0, l1, l2, l3;
        bf16split(ar[i].x, h0, l0); bf16split(ar[i].y, h1, l1);
        bf16split(ar[i].z, h2, l2); bf16split(ar[i].w, h3, l3);
        uint2 uh; uh.x = pack2(h0, h1); uh.y = pack2(h2, h3);
        uint2 ul; ul.x = pack2(l0, l1); ul.y = pack2(l2, l3);
        uint32_t off = (uint32_t)(row * RB + (cb + i * 4) * 2);
        *(uint2*)(stage + off) = uh;
        *(uint2*)(stage + ST_A + off) = ul;
    }
}

__global__ __launch_bounds__(512, 1) void k_mm1(const float* __restrict__ x) {
    extern __shared__ char smc[];
    uint32_t sb = smem_u32(smc);
    float* hh_sm = (float*)(smc + 2 * STAGE);
    int tid = threadIdx.x, lane = tid & 31, warp = tid >> 5;
    int wm = warp & 3, wn = warp >> 2, g = lane >> 2, tig = lane & 3;
    uint32_t aOff = (uint32_t)((wm * 32 + ((lane >> 3) & 1) * 8 + (lane & 7)) * RB + (lane >> 4) * 16);
    uint32_t bOff = (uint32_t)((wn * 64 + ((lane >> 4) & 1) * 8 + (lane & 7)) * RB + ((lane >> 3) & 1) * 16);
    const float* Asrc = x + (size_t)blockIdx.x * 128 * D_IN;

    float acc[2][8][4] = {};
    float4 ar[2];

    mm1_fillB(sb, 0);
    mm1_loadA(ar, Asrc, 0);
    mm1_cvtA(smc, ar);
    CP_COMMIT();

    for (int c = 0; c < 32; c++) {
        uint32_t cb = sb + (uint32_t)(c & 1) * STAGE;
        char* nxt = smc + (size_t)((c + 1) & 1) * STAGE;
        CP_WAIT0();
        __syncthreads();
        if (c < 31) {
            mm1_fillB(sb + (uint32_t)((c + 1) & 1) * STAGE, (c + 1) * 32);
            CP_COMMIT();
            mm1_loadA(ar, Asrc, (c + 1) * 32);
        }
        mma_block(cb, aOff, bOff, acc);
        if (c < 31) mm1_cvtA(nxt, ar);
    }

    // epilogue: bias + hh + bf16 split of h
    float bv0[8], bv1[8];
#pragma unroll
    for (int ni = 0; ni < 8; ni++) {
        int colg = wn * 64 + ni * 8 + tig * 2;
        bv0[ni] = g_b1p[colg]; bv1[ni] = g_b1p[colg + 1];
    }
#pragma unroll
    for (int mi = 0; mi < 2; mi++) {
        int rloc = wm * 32 + mi * 16 + g;
        int rowg = blockIdx.x * 128 + rloc;
        float s0 = 0.f, s1 = 0.f;
#pragma unroll
        for (int ni = 0; ni < 8; ni++) {
            int colg = wn * 64 + ni * 8 + tig * 2;
            float v0 = acc[mi][ni][0] + bv0[ni];
            float v1 = acc[mi][ni][1] + bv1[ni];
            float v2 = acc[mi][ni][2] + bv0[ni];
            float v3 = acc[mi][ni][3] + bv1[ni];
            s0 += v0 * v0 + v1 * v1;
            s1 += v2 * v2 + v3 * v3;
            __nv_bfloat16 h0, h1, l0, l1;
            bf16split(v0, h0, l0); bf16split(v1, h1, l1);
            *(uint32_t*)(g_h_hi + (size_t)rowg * 256 + colg) = pack2(h0, h1);
            *(uint32_t*)(g_h_lo + (size_t)rowg * 256 + colg) = pack2(l0, l1);
            bf16split(v2, h0, l0); bf16split(v3, h1, l1);
            *(uint32_t*)(g_h_hi + (size_t)(rowg + 8) * 256 + colg) = pack2(h0, h1);
            *(uint32_t*)(g_h_lo + (size_t)(rowg + 8) * 256 + colg) = pack2(l0, l1);
        }
        s0 += __shfl_xor_sync(0xffffffffu, s0, 1);
        s0 += __shfl_xor_sync(0xffffffffu, s0, 2);
        s1 += __shfl_xor_sync(0xffffffffu, s1, 1);
        s1 += __shfl_xor_sync(0xffffffffu, s1, 2);
        if (tig == 0) { hh_sm[wn * 128 + rloc] = s0; hh_sm[wn * 128 + rloc + 8] = s1; }
    }
    __syncthreads();
    if (tid < 128) {
        g_hhp[blockIdx.x * 128 + tid] =
            hh_sm[tid] + hh_sm[128 + tid] + hh_sm[256 + tid] + hh_sm[384 + tid];
    }
}

// ================= dist: per-CTA full K_CB, 512 thr, warp 32x64 =================
__device__ __forceinline__ void dist_fill(uint32_t sbuf,
    const __nv_bfloat16* Ah, const __nv_bfloat16* Al, int kOff,
    const __nv_bfloat16* Bh, const __nv_bfloat16* Bl) {
    int tid = threadIdx.x;
    {
        int row = tid >> 2, seg = tid & 3;   // 512 tasks: 128 rows x 4 segs
        uint32_t so = (uint32_t)(row * RB + seg * 16);
        cp16(sbuf + so,        (const char*)(Ah + (size_t)row * E_DIM + kOff) + seg * 16);
        cp16(sbuf + so + ST_A, (const char*)(Al + (size_t)row * E_DIM + kOff) + seg * 16);
    }
#pragma unroll
    for (int j = 0; j < 2; j++) {
        int idx = tid * 2 + j;               // 1024 tasks: 256 rows x 4 segs
        int row = idx >> 2, seg = idx & 3;
        uint32_t so = 2 * ST_A + (uint32_t)(row * RB + seg * 16);
        cp16(sbuf + so,        (const char*)(Bh + (size_t)row * E_DIM + kOff) + seg * 16);
        cp16(sbuf + so + ST_B, (const char*)(Bl + (size_t)row * E_DIM + kOff) + seg * 16);
    }
}

__global__ __launch_bounds__(512, 1) void k_dist() {
    extern __shared__ char smc[];
    uint32_t sb = smem_u32(smc);
    unsigned long long* red = (unsigned long long*)(smc + 2 * STAGE);
    int tid = threadIdx.x, lane = tid & 31, warp = tid >> 5;
    int wm = warp & 3, wn = warp >> 2, g = lane >> 2, tig = lane & 3;
    uint32_t aOff = (uint32_t)((wm * 32 + ((lane >> 3) & 1) * 8 + (lane & 7)) * RB + (lane >> 4) * 16);
    uint32_t bOff = (uint32_t)((wn * 64 + ((lane >> 4) & 1) * 8 + (lane & 7)) * RB + ((lane >> 3) & 1) * 16);
    const __nv_bfloat16* Ah = g_h_hi + (size_t)blockIdx.x * 128 * E_DIM;
    const __nv_bfloat16* Al = g_h_lo + (size_t)blockIdx.x * 128 * E_DIM;

    if (tid < 512) red[tid] = ~0ull;
    __syncthreads();

    for (int nb = 0; nb < 4; nb++) {
        const __nv_bfloat16* Bh = g_emb_hi + (size_t)nb * 256 * E_DIM;
        const __nv_bfloat16* Bl = g_emb_lo + (size_t)nb * 256 * E_DIM;
        float acc[2][8][4] = {};

        dist_fill(sb, Ah, Al, 0, Bh, Bl);
        CP_COMMIT();
        for (int c = 0; c < 8; c++) {
            uint32_t cb = sb + (uint32_t)(c & 1) * STAGE;
            CP_WAIT0();
            __syncthreads();
            if (c < 7) {
                dist_fill(sb + (uint32_t)((c + 1) & 1) * STAGE, Ah, Al, (c + 1) * 32, Bh, Bl);
                CP_COMMIT();
            }
            mma_block(cb, aOff, bOff, acc);
        }

#pragma unroll
        for (int mi = 0; mi < 2; mi++) {
            int rloc = wm * 32 + mi * 16 + g;
            int rowg = blockIdx.x * 128 + rloc;
            float hh0 = g_hhp[rowg];
            float hh1 = g_hhp[rowg + 8];
            unsigned long long b0 = ~0ull, b1 = ~0ull;
#pragma unroll
            for (int ni = 0; ni < 8; ni++) {
                int colg = nb * 256 + wn * 64 + ni * 8 + tig * 2;
                float e0 = g_ee[colg], e1 = g_ee[colg + 1];
                float d0 = __fsub_rn(__fadd_rn(hh0, e0), __fmul_rn(2.0f, acc[mi][ni][0]));
                float d1 = __fsub_rn(__fadd_rn(hh0, e1), __fmul_rn(2.0f, acc[mi][ni][1]));
                float d2 = __fsub_rn(__fadd_rn(hh1, e0), __fmul_rn(2.0f, acc[mi][ni][2]));
                float d3 = __fsub_rn(__fadd_rn(hh1, e1), __fmul_rn(2.0f, acc[mi][ni][3]));
                unsigned long long p;
                p = packdi(d0, colg);     if (p < b0) b0 = p;
                p = packdi(d1, colg + 1); if (p < b0) b0 = p;
                p = packdi(d2, colg);     if (p < b1) b1 = p;
                p = packdi(d3, colg + 1); if (p < b1) b1 = p;
            }
            unsigned long long t;
            t = __shfl_xor_sync(0xffffffffu, b0, 1); if (t < b0) b0 = t;
            t = __shfl_xor_sync(0xffffffffu, b0, 2); if (t < b0) b0 = t;
            t = __shfl_xor_sync(0xffffffffu, b1, 1); if (t < b1) b1 = t;
            t = __shfl_xor_sync(0xffffffffu, b1, 2); if (t < b1) b1 = t;
            if (tig == 0) {
                unsigned long long* r0 = &red[wn * 128 + rloc];
                unsigned long long* r1 = &red[wn * 128 + rloc + 8];
                if (b0 < *r0) *r0 = b0;
                if (b1 < *r1) *r1 = b1;
            }
        }
        __syncthreads();
    }

    if (tid < 128) {
        unsigned long long m = red[tid];
        unsigned long long v;
        v = red[128 + tid]; if (v < m) m = v;
        v = red[256 + tid]; if (v < m) m = v;
        v = red[384 + tid]; if (v < m) m = v;
        g_amin[blockIdx.x * 128 + tid] = m;
    }
}

// ================= rest of pipeline (validated) =================
__global__ void k_histo() {
    __shared__ int sh[K_CB];
    int t = threadIdx.x;
    for (int i = t; i < K_CB; i += 256) sh[i] = 0;
    __syncthreads();
    int n = blockIdx.x * 256 + t;
    int idx = (int)(g_amin[n] & 0xFFFFFFFFull);
    atomicAdd(&sh[idx], 1);
    __syncthreads();
    for (int i = t; i < K_CB; i += 256) if (sh[i]) atomicAdd(&g_hist[i], sh[i]);
}

__global__ void k_bn2(const float* __restrict__ emb,
                      const float* __restrict__ gamma2, const float* __restrict__ beta2) {
    int e = blockIdx.x, t = threadIdx.x;
    float s1 = 0.f, s2 = 0.f;
#pragma unroll
    for (int j = 0; j < 4; j++) {
        int k = j * 256 + t;
        float c = (float)g_hist[k];
        float v = emb[(size_t)k * E_DIM + e];
        s1 += c * v; s2 += c * v * v;
    }
    __shared__ float a1[256], a2[256];
    a1[t] = s1; a2[t] = s2; __syncthreads();
    for (int s = 128; s > 0; s >>= 1) {
        if (t < s) { a1[t] += a1[t + s]; a2[t] += a2[t + s]; }
        __syncthreads();
    }
    if (t == 0) {
        float mu  = a1[0] / (float)N_TOK;
        float var = a2[0] / (float)N_TOK - mu * mu;
        float sc = gamma2[e] * rsqrtf(var + EPS);
        g_scale2[e] = sc;
        g_shift2[e] = beta2[e] - mu * sc;
    }
}

__global__ void k_qn(const float* __restrict__ emb) {
    int i = blockIdx.x * 256 + threadIdx.x;
    int e = i & (E_DIM - 1);
    g_qn[i] = emb[i] * g_scale2[e] + g_shift2[e];
}

__global__ void k_gemm2(const float* __restrict__ w2, const float* __restrict__ b2) {
    __shared__ float As[16][128];
    __shared__ float Bs[16][128];
    float acc[8][8] = {};
    int tid = threadIdx.x;
    int tx = tid & 15, ty = tid >> 4;
    const float* Ab = g_qn + (size_t)(blockIdx.x * 128) * E_DIM;
    const float* Bb = w2 + (size_t)(blockIdx.y * 128) * E_DIM;
    for (int k0 = 0; k0 < E_DIM; k0 += 16) {
#pragma unroll
        for (int i = 0; i < 2; i++) {
            int id  = tid + i * 256;
            int row = id >> 2;
            int kq  = (id & 3) << 2;
            float4 va = *(const float4*)(Ab + (size_t)row * E_DIM + k0 + kq);
            As[kq + 0][row] = va.x; As[kq + 1][row] = va.y;
            As[kq + 2][row] = va.z; As[kq + 3][row] = va.w;
            float4 vb = *(const float4*)(Bb + (size_t)row * E_DIM + k0 + kq);
            Bs[kq + 0][row] = vb.x; Bs[kq + 1][row] = vb.y;
            Bs[kq + 2][row] = vb.z; Bs[kq + 3][row] = vb.w;
        }
        __syncthreads();
#pragma unroll
        for (int kk = 0; kk < 16; kk++) {
            float ra[8], rb[8];
            *(float4*)&ra[0] = *(const float4*)&As[kk][ty * 8];
            *(float4*)&ra[4] = *(const float4*)&As[kk][ty * 8 + 4];
            *(float4*)&rb[0] = *(const float4*)&Bs[kk][tx * 8];
            *(float4*)&rb[4] = *(const float4*)&Bs[kk][tx * 8 + 4];
#pragma unroll
            for (int i = 0; i < 8; i++)
#pragma unroll
                for (int j = 0; j < 8; j++)
                    acc[i][j] += ra[i] * rb[j];
        }
        __syncthreads();
    }
    int colBase = blockIdx.y * 128 + tx * 8;
#pragma unroll
    for (int i = 0; i < 8; i++) {
        size_t row = (size_t)blockIdx.x * 128 + ty * 8 + i;
        float4 v0, v1;
        v0.x = acc[i][0] + b2[colBase + 0]; v0.y = acc[i][1] + b2[colBase + 1];
        v0.z = acc[i][2] + b2[colBase + 2]; v0.w = acc[i][3] + b2[colBase + 3];
        v1.x = acc[i][4] + b2[colBase + 4]; v1.y = acc[i][5] + b2[colBase + 5];
        v1.z = acc[i][6] + b2[colBase + 6]; v1.w = acc[i][7] + b2[colBase + 7];
        *(float4*)(g_ocb + row * D_IN + colBase)     = v0;
        *(float4*)(g_ocb + row * D_IN + colBase + 4) = v1;
    }
}

__global__ void k_final(const float* __restrict__ x, float* __restrict__ out) {
    int t = threadIdx.x;
    float* outq = out + 1;
    double accd = 0.0;
#pragma unroll
    for (int r = 0; r < 8; r++) {
        int n = blockIdx.x * 8 + r;
        int idx = (int)(g_amin[n] & 0xFFFFFFFFull);
        float4 q  = ((const float4*)(g_ocb + (size_t)idx * D_IN))[t];
        float4 xv = ((const float4*)(x + (size_t)n * D_IN))[t];
        float dx = __fsub_rn(q.x, xv.x);
        float dy = __fsub_rn(q.y, xv.y);
        float dz = __fsub_rn(q.z, xv.z);
        float dw = __fsub_rn(q.w, xv.w);
        float* o = outq + (size_t)n * D_IN + t * 4;
        o[0] = __fadd_rn(xv.x, dx);
        o[1] = __fadd_rn(xv.y, dy);
        o[2] = __fadd_rn(xv.z, dz);
        o[3] = __fadd_rn(xv.w, dw);
        accd += (double)dx * dx + (double)dy * dy + (double)dz * dz + (double)dw * dw;
    }
    __shared__ double sd[256];
    sd[t] = accd; __syncthreads();
    for (int s = 128; s > 0; s >>= 1) { if (t < s) sd[t] += sd[t + s]; __syncthreads(); }
    if (t == 0) atomicAdd(&g_loss, sd[0]);
}

__global__ void k_small(float* __restrict__ out) {
    int i = blockIdx.x * 256 + threadIdx.x;
    size_t OFF_U = 1 + (size_t)N_TOK * D_IN;
    if (i == 0) out[0] = (float)(1.25 * g_loss / ((double)N_TOK * (double)D_IN));
    if (i < K_CB) out[OFF_U + i] = (float)g_hist[i] / (float)N_TOK;
}

__global__ void k_embcopy(const float* __restrict__ emb, float* __restrict__ out) {
    size_t OFF_E = 1 + (size_t)N_TOK * D_IN + K_CB;
    int i = blockIdx.x * 256 + threadIdx.x;
    out[OFF_E + i] = emb[i];
}

// ================= launch =================
extern "C" void kernel_launch(void* const* d_in, const int* in_sizes, int n_in,
                              void* d_out, int out_size) {
    (void)in_sizes; (void)n_in; (void)out_size;
    const float* x      = (const float*)d_in[0];
    const float* emb    = (const float*)d_in[1];
    const float* w1     = (const float*)d_in[2];
    const float* b1     = (const float*)d_in[3];
    const float* w2     = (const float*)d_in[4];
    const float* b2     = (const float*)d_in[5];
    const float* gamma1 = (const float*)d_in[6];
    const float* beta1  = (const float*)d_in[7];
    const float* gamma2 = (const float*)d_in[8];
    const float* beta2  = (const float*)d_in[9];
    float* out = (float*)d_out;

    cudaFuncSetAttribute(k_mm1,  cudaFuncAttributeMaxDynamicSharedMemorySize, MM1_SMEM);
    cudaFuncSetAttribute(k_dist, cudaFuncAttributeMaxDynamicSharedMemorySize, DIST_SMEM);

    k_colstats<<<dim3(D_IN / 256, SLABS), 256>>>(x);        // 0
    k_bn1fin<<<D_IN / 256, 256>>>(gamma1, beta1);           // 1
    k_fold<<<E_DIM, 256>>>(w1, b1);                         // 2
    k_mm1<<<N_TOK / 128, 512, MM1_SMEM>>>(x);               // 3  <- ncu slot
    k_ee<<<K_CB / 8, 256>>>(emb);                           // 4
    k_dist<<<N_TOK / 128, 512, DIST_SMEM>>>();              // 5
    k_init<<<4, 256>>>();                                   // 6
    k_histo<<<N_TOK / 256, 256>>>();                        // 7
    k_bn2<<<E_DIM, 256>>>(emb, gamma2, beta2);              // 8
    k_qn<<<(K_CB * E_DIM) / 256, 256>>>(emb);               // 9
    k_gemm2<<<dim3(K_CB / 128, D_IN / 128), 256>>>(w2, b2); // 10
    k_final<<<N_TOK / 8, 256>>>(x, out);                    // 11
    k_small<<<4, 256>>>(out);                               // 12
    k_embcopy<<<(K_CB * E_DIM) / 256, 256>>>(emb, out);     // 13
}